// round 10
// baseline (speedup 1.0000x reference)
#include <cuda_runtime.h>
#include <stdint.h>

#define KOUT 49
#define MAXT 32
#define SAMPLES_PER_BLK 32
#define THREADS_PER_BLK 224              // 7 warps: warp w -> mu = w, lane -> sample
// Lane blob: X1 rows padded to 8 floats (words 0..55), X2 rows padded (56..111), pad 4.
// XSTR = 116 = 4*29: 16B-aligned lane bases; for LDS.128 each 8-lane phase hits
// banks {0,20,8,28,16,4,24,12}+k -> conflict-free.
#define XSTR 116
#define X2B 224                          // byte offset of X2 row 0 in lane blob (56 words)
#define OBASE (SAMPLES_PER_BLK * XSTR)   // 3712 words
#define OUTSTR 33
#define SMEM_WORDS (OBASE + KOUT * OUTSTR)   // 5329 words = 21316 B

// ---- device tables built by setup kernel each launch ----
// One uint4 per (mu, r2-group): {x1_row_byteoff_a, c_a_bits, x1_row_byteoff_b, c_b_bits}.
// Generator emits exactly <=2 terms per (mu, m2) (re*re + im*im; compress only
// merges) — validated R8/R9 (identical rel_err). c=0 pads, offset 0 (harmless).
__device__ __align__(16) uint4 g_gslot[49];
__device__ float g_D[KOUT * 8];      // dense stage-2: D[i][mup], i = m1p*7+m2p, row padded to 8

// ---------------------------------------------------------------------------
// Setup (fully parallel): recover factorized term lists from the aligned
// product arrays. Generation order is (mu, t, mup, t'):
//   focc[v] (v<7) -> start of (mu=0,t=0,mup=v) run ; focc[mu*7] -> mu segment
//   T[v] = focc[v+1]-focc[v] (v<6); T[6] = focc[7]/T[0] - focc[6]; Ttot = focc[6]+T[6]
// Coefficients from products only (A = mult[0] = c0^2):
//   c_hat(mu,t)   = mult[seg(mu) + t*Ttot]   (= c_t * c0)
//   d_hat(mup,t') = mult[focc[mup] + t'] / A (= c_t' / c0)   =>  c_hat*d_hat exact.
// ---------------------------------------------------------------------------
__global__ void wigner_setup(const float* __restrict__ mult,
                             const int* __restrict__ m1,  const int* __restrict__ m1p,
                             const int* __restrict__ m2,  const int* __restrict__ m2p,
                             const int* __restrict__ mub, int n)
{
    __shared__ int focc[KOUT];
    __shared__ int sT[8];
    __shared__ int cnt[49];
    int tid = threadIdx.x;
    if (tid < KOUT) { focc[tid] = 0x7fffffff; cnt[tid] = 0; }
    if (tid < 49) g_gslot[tid] = make_uint4(0u, 0u, 0u, 0u);
    for (int i = tid; i < KOUT * 8; i += blockDim.x) g_D[i] = 0.0f;
    __syncthreads();
    for (int j = tid; j < n; j += blockDim.x)
        atomicMin(&focc[mub[j]], j);
    __syncthreads();
    if (tid == 0) {
        int T0 = focc[1] - focc[0];
        sT[0] = T0;
        for (int v = 1; v < 6; v++) sT[v] = focc[v + 1] - focc[v];
        int t6 = focc[7] / T0 - focc[6];
        sT[6] = t6;
        sT[7] = focc[6] + t6;                       // Ttot
        for (int v = 0; v < 7; v++) if (sT[v] > MAXT) sT[v] = MAXT;
    }
    __syncthreads();
    float A = mult[0];
    int Ttot = sT[7];
    int mu = tid >> 5, t = tid & 31;
    if (tid < 7 * MAXT && t < sT[mu]) {
        int j = focc[mu * 7] + t * Ttot;                   // (mu, t, 0, 0)
        int r2 = m2[j];
        int pos = atomicAdd(&cnt[mu * 7 + r2], 1);
        if (pos < 2) {
            unsigned* slot = (unsigned*)&g_gslot[mu * 7 + r2];
            slot[pos * 2]     = (unsigned)(m1[j] * 32);    // padded 8-float rows
            slot[pos * 2 + 1] = __float_as_uint(mult[j]);
        }
        int j2 = focc[mu] + t;                              // (0, 0, mup=mu, t')
        atomicAdd(&g_D[(m1p[j2] * 7 + m2p[j2]) * 8 + mu], mult[j2] / A);
    }
}

// ---------------------------------------------------------------------------
// Main: thread = (sample, mu). Stage 1: u-factorization
//   W[a,b] = sum_g u_g[a] * X2[g][b],  u_g[a] = c0 X1[ra][a] + c1 X1[rb][a]
// with ALL X accesses as LDS.128 (rows padded to 8 floats): per group per pass
// just 5 vector loads. Rolled 7-group loops keep live set < 72 regs (no
// spills, R8 lesson). Two a-half passes, each consumed immediately against the
// dense D matrix (compile-time indices, W never leaves registers).
// ---------------------------------------------------------------------------
__global__ void __launch_bounds__(THREADS_PER_BLK, 4)
wigner_main(const float* __restrict__ X1, const float* __restrict__ X2,
            float* __restrict__ out, int N)
{
    __shared__ __align__(16) float sm[SMEM_WORDS];
    __shared__ __align__(16) uint4 s_gslot[49];
    __shared__ __align__(16) float s_D[KOUT * 8];

    int tid  = threadIdx.x;
    int lane = tid & 31;
    int mu   = tid >> 5;
    int base = blockIdx.x * SAMPLES_PER_BLK;
    int nvalid = N - base; if (nvalid > SAMPLES_PER_BLK) nvalid = SAMPLES_PER_BLK;

    const float* g1 = X1 + (size_t)base * KOUT;
    const float* g2 = X2 + (size_t)base * KOUT;

    if (nvalid == SAMPLES_PER_BLK) {
        float r1v[7], r2v[7];
        #pragma unroll
        for (int k = 0; k < 7; k++) {
            int i = tid + k * THREADS_PER_BLK;
            r1v[k] = g1[i];
            r2v[k] = g2[i];
        }
        if (tid < 49) s_gslot[tid] = g_gslot[tid];
        s_D[tid] = g_D[tid];
        if (tid < KOUT * 8 - THREADS_PER_BLK) s_D[tid + THREADS_PER_BLK] = g_D[tid + THREADS_PER_BLK];
        #pragma unroll
        for (int k = 0; k < 7; k++) {
            int i = tid + k * THREADS_PER_BLK;
            int s = i / KOUT;
            int c = i - s * KOUT;
            int r = c / 7, a = c - r * 7;
            sm[s * XSTR + r * 8 + a]      = r1v[k];
            sm[s * XSTR + 56 + r * 8 + a] = r2v[k];
        }
    } else {
        if (tid < 49) s_gslot[tid] = g_gslot[tid];
        s_D[tid] = g_D[tid];
        if (tid < KOUT * 8 - THREADS_PER_BLK) s_D[tid + THREADS_PER_BLK] = g_D[tid + THREADS_PER_BLK];
        int total = nvalid * KOUT;
        for (int i = tid; i < total; i += THREADS_PER_BLK) {
            int s = i / KOUT;
            int c = i - s * KOUT;
            int r = c / 7, a = c - r * 7;
            sm[s * XSTR + r * 8 + a]      = g1[i];
            sm[s * XSTR + 56 + r * 8 + a] = g2[i];
        }
    }
    __syncthreads();

    if (lane < nvalid) {
        const char* xc = (const char*)(sm + lane * XSTR);
        const uint4* gs = s_gslot + mu * 7;
        float acc[7];
        #pragma unroll
        for (int q = 0; q < 7; q++) acc[q] = 0.0f;

        // ================= PASS A : rows a = 0..3 =================
        {
            float WA[28];
            #pragma unroll
            for (int i = 0; i < 28; i++) WA[i] = 0.0f;
            #pragma unroll 1
            for (int g = 0; g < 7; g++) {
                uint4 e = gs[g];                                   // uniform LDS.128
                float c0 = __uint_as_float(e.y);
                float c1 = __uint_as_float(e.w);
                float4 ra = *(const float4*)(xc + e.x);            // X1[ra][0..3]
                float4 rb = *(const float4*)(xc + e.z);
                float u0 = fmaf(c1, rb.x, c0 * ra.x);
                float u1 = fmaf(c1, rb.y, c0 * ra.y);
                float u2 = fmaf(c1, rb.z, c0 * ra.z);
                float u3 = fmaf(c1, rb.w, c0 * ra.w);
                float4 x2a = *(const float4*)(xc + X2B + g * 32);      // X2[g][0..3]
                float4 x2b = *(const float4*)(xc + X2B + g * 32 + 16); // X2[g][4..6],pad
                float xv[7] = {x2a.x, x2a.y, x2a.z, x2a.w, x2b.x, x2b.y, x2b.z};
                #pragma unroll
                for (int b = 0; b < 7; b++) {
                    float x = xv[b];
                    WA[0 * 7 + b] = fmaf(u0, x, WA[0 * 7 + b]);
                    WA[1 * 7 + b] = fmaf(u1, x, WA[1 * 7 + b]);
                    WA[2 * 7 + b] = fmaf(u2, x, WA[2 * 7 + b]);
                    WA[3 * 7 + b] = fmaf(u3, x, WA[3 * 7 + b]);
                }
            }
            #pragma unroll
            for (int i = 0; i < 28; i++) {
                float4 d0 = *(const float4*)(s_D + i * 8);     // uniform broadcast
                float4 d1 = *(const float4*)(s_D + i * 8 + 4);
                float w = WA[i];
                acc[0] = fmaf(d0.x, w, acc[0]);
                acc[1] = fmaf(d0.y, w, acc[1]);
                acc[2] = fmaf(d0.z, w, acc[2]);
                acc[3] = fmaf(d0.w, w, acc[3]);
                acc[4] = fmaf(d1.x, w, acc[4]);
                acc[5] = fmaf(d1.y, w, acc[5]);
                acc[6] = fmaf(d1.z, w, acc[6]);
            }
        }

        // ================= PASS B : rows a = 4..6 =================
        {
            float WB[21];
            #pragma unroll
            for (int i = 0; i < 21; i++) WB[i] = 0.0f;
            #pragma unroll 1
            for (int g = 0; g < 7; g++) {
                uint4 e = gs[g];
                float c0 = __uint_as_float(e.y);
                float c1 = __uint_as_float(e.w);
                float4 ra = *(const float4*)(xc + e.x + 16);       // X1[ra][4..6],pad
                float4 rb = *(const float4*)(xc + e.z + 16);
                float u4 = fmaf(c1, rb.x, c0 * ra.x);
                float u5 = fmaf(c1, rb.y, c0 * ra.y);
                float u6 = fmaf(c1, rb.z, c0 * ra.z);
                float4 x2a = *(const float4*)(xc + X2B + g * 32);
                float4 x2b = *(const float4*)(xc + X2B + g * 32 + 16);
                float xv[7] = {x2a.x, x2a.y, x2a.z, x2a.w, x2b.x, x2b.y, x2b.z};
                #pragma unroll
                for (int b = 0; b < 7; b++) {
                    float x = xv[b];
                    WB[0 * 7 + b] = fmaf(u4, x, WB[0 * 7 + b]);
                    WB[1 * 7 + b] = fmaf(u5, x, WB[1 * 7 + b]);
                    WB[2 * 7 + b] = fmaf(u6, x, WB[2 * 7 + b]);
                }
            }
            #pragma unroll
            for (int i = 0; i < 21; i++) {
                float4 d0 = *(const float4*)(s_D + (28 + i) * 8);
                float4 d1 = *(const float4*)(s_D + (28 + i) * 8 + 4);
                float w = WB[i];
                acc[0] = fmaf(d0.x, w, acc[0]);
                acc[1] = fmaf(d0.y, w, acc[1]);
                acc[2] = fmaf(d0.z, w, acc[2]);
                acc[3] = fmaf(d0.w, w, acc[3]);
                acc[4] = fmaf(d1.x, w, acc[4]);
                acc[5] = fmaf(d1.y, w, acc[5]);
                acc[6] = fmaf(d1.z, w, acc[6]);
            }
        }

        // stage output transposed (stride 33 odd -> conflict-free)
        #pragma unroll
        for (int mup = 0; mup < 7; mup++)
            sm[OBASE + (mu * 7 + mup) * OUTSTR + lane] = acc[mup];
    }
    __syncthreads();

    // coalesced flush
    int total = nvalid * KOUT;
    float* go = out + (size_t)base * KOUT;
    for (int i = tid; i < total; i += THREADS_PER_BLK) {
        int s = i / KOUT;
        int c = i - s * KOUT;
        go[i] = sm[OBASE + c * OUTSTR + s];
    }
}

// ---------------------------------------------------------------------------
extern "C" void kernel_launch(void* const* d_in, const int* in_sizes, int n_in,
                              void* d_out, int out_size)
{
    const float* X1   = (const float*)d_in[0];
    const float* X2   = (const float*)d_in[1];
    const float* mult = (const float*)d_in[2];
    const int*   m1   = (const int*)d_in[3];
    const int*   m1p  = (const int*)d_in[4];
    const int*   m2   = (const int*)d_in[5];
    const int*   m2p  = (const int*)d_in[6];
    const int*   mub  = (const int*)d_in[7];

    int n_aligned = in_sizes[2];
    int N = in_sizes[0] / KOUT;

    wigner_setup<<<1, 256>>>(mult, m1, m1p, m2, m2p, mub, n_aligned);

    int grid = (N + SAMPLES_PER_BLK - 1) / SAMPLES_PER_BLK;
    wigner_main<<<grid, THREADS_PER_BLK>>>(X1, X2, (float*)d_out, N);
}

// round 11
// speedup vs baseline: 1.0833x; 1.0833x over previous
#include <cuda_runtime.h>
#include <stdint.h>

#define KOUT 49
#define MAXT 32
#define SAMPLES_PER_BLK 64               // 2 samples per thread: lane and lane+32
#define THREADS_PER_BLK 224              // 7 warps: warp w -> mu = w
#define XSTR 99                          // per-sample X blob: X1[0..48], X2[49..97], pad (odd -> conflict-free)
#define X2B 196                          // byte offset of X2 row 0 in blob
#define OBASE (SAMPLES_PER_BLK * XSTR)   // 6336 words
#define OUTSTR 65                        // odd -> conflict-free transposed staging
#define SMEM_WORDS (OBASE + KOUT * OUTSTR)   // 9521 words = 38084 B

// ---- device tables built by setup kernel each launch ----
// One uint4 per (mu, r2-group): {x1_row_byteoff_a, c_a_bits, x1_row_byteoff_b, c_b_bits}.
// Generator emits exactly <=2 terms per (mu, m2) (re*re + im*im; compress only
// merges) — validated R8/R9/R10 (identical rel_err). c=0 pads, offset 0.
__device__ __align__(16) uint4 g_gslot[49];
__device__ float g_D[KOUT * 8];      // dense stage-2: D[i][mup], i = m1p*7+m2p, row padded to 8

// ---------------------------------------------------------------------------
// Setup (fully parallel): recover factorized term lists from the aligned
// product arrays. Generation order is (mu, t, mup, t'):
//   focc[v] (v<7) -> start of (mu=0,t=0,mup=v) run ; focc[mu*7] -> mu segment
//   T[v] = focc[v+1]-focc[v] (v<6); T[6] = focc[7]/T[0] - focc[6]; Ttot = focc[6]+T[6]
// Coefficients from products only (A = mult[0] = c0^2):
//   c_hat(mu,t)   = mult[seg(mu) + t*Ttot]   (= c_t * c0)
//   d_hat(mup,t') = mult[focc[mup] + t'] / A (= c_t' / c0)   =>  c_hat*d_hat exact.
// ---------------------------------------------------------------------------
__global__ void wigner_setup(const float* __restrict__ mult,
                             const int* __restrict__ m1,  const int* __restrict__ m1p,
                             const int* __restrict__ m2,  const int* __restrict__ m2p,
                             const int* __restrict__ mub, int n)
{
    __shared__ int focc[KOUT];
    __shared__ int sT[8];
    __shared__ int cnt[49];
    int tid = threadIdx.x;
    if (tid < KOUT) { focc[tid] = 0x7fffffff; cnt[tid] = 0; }
    if (tid < 49) g_gslot[tid] = make_uint4(0u, 0u, 0u, 0u);
    for (int i = tid; i < KOUT * 8; i += blockDim.x) g_D[i] = 0.0f;
    __syncthreads();
    for (int j = tid; j < n; j += blockDim.x)
        atomicMin(&focc[mub[j]], j);
    __syncthreads();
    if (tid == 0) {
        int T0 = focc[1] - focc[0];
        sT[0] = T0;
        for (int v = 1; v < 6; v++) sT[v] = focc[v + 1] - focc[v];
        int t6 = focc[7] / T0 - focc[6];
        sT[6] = t6;
        sT[7] = focc[6] + t6;                       // Ttot
        for (int v = 0; v < 7; v++) if (sT[v] > MAXT) sT[v] = MAXT;
    }
    __syncthreads();
    float A = mult[0];
    int Ttot = sT[7];
    int mu = tid >> 5, t = tid & 31;
    if (tid < 7 * MAXT && t < sT[mu]) {
        int j = focc[mu * 7] + t * Ttot;                   // (mu, t, 0, 0)
        int r2 = m2[j];
        int pos = atomicAdd(&cnt[mu * 7 + r2], 1);
        if (pos < 2) {
            unsigned* slot = (unsigned*)&g_gslot[mu * 7 + r2];
            slot[pos * 2]     = (unsigned)(m1[j] * 28);    // 7-float rows, byte offsets
            slot[pos * 2 + 1] = __float_as_uint(mult[j]);
        }
        int j2 = focc[mu] + t;                              // (0, 0, mup=mu, t')
        atomicAdd(&g_D[(m1p[j2] * 7 + m2p[j2]) * 8 + mu], mult[j2] / A);
    }
}

// ---------------------------------------------------------------------------
// Main: thread = (lane, mu) processing TWO samples (lane, lane+32) — two
// independent LDS->FMA chains interleaved for 2x ILP; uniform loads (group
// slots, dense D rows) shared between both samples. Two a-half passes keep
// peak live regs ~90 (< 96-reg cap at 3 blocks/SM -> no spills). Group loop
// stays rolled (R8 lesson). Dense-D consume: W never leaves registers.
// ---------------------------------------------------------------------------
__global__ void __launch_bounds__(THREADS_PER_BLK, 3)
wigner_main(const float* __restrict__ X1, const float* __restrict__ X2,
            float* __restrict__ out, int N)
{
    __shared__ float sm[SMEM_WORDS];
    __shared__ __align__(16) uint4 s_gslot[49];
    __shared__ __align__(16) float s_D[KOUT * 8];

    int tid  = threadIdx.x;
    int lane = tid & 31;
    int mu   = tid >> 5;
    int base = blockIdx.x * SAMPLES_PER_BLK;
    int nvalid = N - base; if (nvalid > SAMPLES_PER_BLK) nvalid = SAMPLES_PER_BLK;
    int total = nvalid * KOUT;

    const float* g1 = X1 + (size_t)base * KOUT;
    const float* g2 = X2 + (size_t)base * KOUT;

    // ---- staging: batched LDG (MLP=28) + table copies overlap the loads ----
    if (nvalid == SAMPLES_PER_BLK) {
        float r1v[14], r2v[14];
        #pragma unroll
        for (int k = 0; k < 14; k++) {
            int i = tid + k * THREADS_PER_BLK;
            r1v[k] = g1[i];
            r2v[k] = g2[i];
        }
        if (tid < 49) s_gslot[tid] = g_gslot[tid];
        s_D[tid] = g_D[tid];
        if (tid < KOUT * 8 - THREADS_PER_BLK) s_D[tid + THREADS_PER_BLK] = g_D[tid + THREADS_PER_BLK];
        #pragma unroll
        for (int k = 0; k < 14; k++) {
            int i = tid + k * THREADS_PER_BLK;
            int s = i / KOUT;
            int c = i - s * KOUT;
            sm[s * XSTR + c]      = r1v[k];
            sm[s * XSTR + 49 + c] = r2v[k];
        }
    } else {
        if (tid < 49) s_gslot[tid] = g_gslot[tid];
        s_D[tid] = g_D[tid];
        if (tid < KOUT * 8 - THREADS_PER_BLK) s_D[tid + THREADS_PER_BLK] = g_D[tid + THREADS_PER_BLK];
        for (int i = tid; i < OBASE; i += THREADS_PER_BLK) sm[i] = 0.0f;  // zero invalid blobs
        __syncthreads();
        for (int i = tid; i < total; i += THREADS_PER_BLK) {
            int s = i / KOUT;
            int c = i - s * KOUT;
            sm[s * XSTR + c]      = g1[i];
            sm[s * XSTR + 49 + c] = g2[i];
        }
    }
    __syncthreads();

    {
        const char* xc0 = (const char*)(sm + lane * XSTR);
        const char* xc1 = (const char*)(sm + (lane + 32) * XSTR);
        const uint4* gs = s_gslot + mu * 7;
        float acc0[7], acc1[7];
        #pragma unroll
        for (int q = 0; q < 7; q++) { acc0[q] = 0.0f; acc1[q] = 0.0f; }

        // ================= PASS A : rows a = 0..3 =================
        {
            float WA0[28], WA1[28];
            #pragma unroll
            for (int i = 0; i < 28; i++) { WA0[i] = 0.0f; WA1[i] = 0.0f; }
            #pragma unroll 1
            for (int g = 0; g < 7; g++) {
                uint4 e = gs[g];                               // uniform
                float c0 = __uint_as_float(e.y);
                float c1 = __uint_as_float(e.w);
                const float* ra0 = (const float*)(xc0 + e.x);
                const float* rb0 = (const float*)(xc0 + e.z);
                const float* ra1 = (const float*)(xc1 + e.x);
                const float* rb1 = (const float*)(xc1 + e.z);
                float u00 = fmaf(c1, rb0[0], c0 * ra0[0]);
                float u01 = fmaf(c1, rb0[1], c0 * ra0[1]);
                float u02 = fmaf(c1, rb0[2], c0 * ra0[2]);
                float u03 = fmaf(c1, rb0[3], c0 * ra0[3]);
                float u10 = fmaf(c1, rb1[0], c0 * ra1[0]);
                float u11 = fmaf(c1, rb1[1], c0 * ra1[1]);
                float u12 = fmaf(c1, rb1[2], c0 * ra1[2]);
                float u13 = fmaf(c1, rb1[3], c0 * ra1[3]);
                const float* r20 = (const float*)(xc0 + X2B + g * 28);
                const float* r21 = (const float*)(xc1 + X2B + g * 28);
                #pragma unroll
                for (int b = 0; b < 7; b++) {
                    float x0 = r20[b];
                    float x1 = r21[b];
                    WA0[0 * 7 + b] = fmaf(u00, x0, WA0[0 * 7 + b]);
                    WA1[0 * 7 + b] = fmaf(u10, x1, WA1[0 * 7 + b]);
                    WA0[1 * 7 + b] = fmaf(u01, x0, WA0[1 * 7 + b]);
                    WA1[1 * 7 + b] = fmaf(u11, x1, WA1[1 * 7 + b]);
                    WA0[2 * 7 + b] = fmaf(u02, x0, WA0[2 * 7 + b]);
                    WA1[2 * 7 + b] = fmaf(u12, x1, WA1[2 * 7 + b]);
                    WA0[3 * 7 + b] = fmaf(u03, x0, WA0[3 * 7 + b]);
                    WA1[3 * 7 + b] = fmaf(u13, x1, WA1[3 * 7 + b]);
                }
            }
            #pragma unroll
            for (int i = 0; i < 28; i++) {
                float4 d0 = *(const float4*)(s_D + i * 8);     // uniform, shared by both samples
                float4 d1 = *(const float4*)(s_D + i * 8 + 4);
                float w0 = WA0[i], w1 = WA1[i];
                acc0[0] = fmaf(d0.x, w0, acc0[0]);  acc1[0] = fmaf(d0.x, w1, acc1[0]);
                acc0[1] = fmaf(d0.y, w0, acc0[1]);  acc1[1] = fmaf(d0.y, w1, acc1[1]);
                acc0[2] = fmaf(d0.z, w0, acc0[2]);  acc1[2] = fmaf(d0.z, w1, acc1[2]);
                acc0[3] = fmaf(d0.w, w0, acc0[3]);  acc1[3] = fmaf(d0.w, w1, acc1[3]);
                acc0[4] = fmaf(d1.x, w0, acc0[4]);  acc1[4] = fmaf(d1.x, w1, acc1[4]);
                acc0[5] = fmaf(d1.y, w0, acc0[5]);  acc1[5] = fmaf(d1.y, w1, acc1[5]);
                acc0[6] = fmaf(d1.z, w0, acc0[6]);  acc1[6] = fmaf(d1.z, w1, acc1[6]);
            }
        }

        // ================= PASS B : rows a = 4..6 =================
        {
            float WB0[21], WB1[21];
            #pragma unroll
            for (int i = 0; i < 21; i++) { WB0[i] = 0.0f; WB1[i] = 0.0f; }
            #pragma unroll 1
            for (int g = 0; g < 7; g++) {
                uint4 e = gs[g];
                float c0 = __uint_as_float(e.y);
                float c1 = __uint_as_float(e.w);
                const float* ra0 = (const float*)(xc0 + e.x);
                const float* rb0 = (const float*)(xc0 + e.z);
                const float* ra1 = (const float*)(xc1 + e.x);
                const float* rb1 = (const float*)(xc1 + e.z);
                float u04 = fmaf(c1, rb0[4], c0 * ra0[4]);
                float u05 = fmaf(c1, rb0[5], c0 * ra0[5]);
                float u06 = fmaf(c1, rb0[6], c0 * ra0[6]);
                float u14 = fmaf(c1, rb1[4], c0 * ra1[4]);
                float u15 = fmaf(c1, rb1[5], c0 * ra1[5]);
                float u16 = fmaf(c1, rb1[6], c0 * ra1[6]);
                const float* r20 = (const float*)(xc0 + X2B + g * 28);
                const float* r21 = (const float*)(xc1 + X2B + g * 28);
                #pragma unroll
                for (int b = 0; b < 7; b++) {
                    float x0 = r20[b];
                    float x1 = r21[b];
                    WB0[0 * 7 + b] = fmaf(u04, x0, WB0[0 * 7 + b]);
                    WB1[0 * 7 + b] = fmaf(u14, x1, WB1[0 * 7 + b]);
                    WB0[1 * 7 + b] = fmaf(u05, x0, WB0[1 * 7 + b]);
                    WB1[1 * 7 + b] = fmaf(u15, x1, WB1[1 * 7 + b]);
                    WB0[2 * 7 + b] = fmaf(u06, x0, WB0[2 * 7 + b]);
                    WB1[2 * 7 + b] = fmaf(u16, x1, WB1[2 * 7 + b]);
                }
            }
            #pragma unroll
            for (int i = 0; i < 21; i++) {
                float4 d0 = *(const float4*)(s_D + (28 + i) * 8);
                float4 d1 = *(const float4*)(s_D + (28 + i) * 8 + 4);
                float w0 = WB0[i], w1 = WB1[i];
                acc0[0] = fmaf(d0.x, w0, acc0[0]);  acc1[0] = fmaf(d0.x, w1, acc1[0]);
                acc0[1] = fmaf(d0.y, w0, acc0[1]);  acc1[1] = fmaf(d0.y, w1, acc1[1]);
                acc0[2] = fmaf(d0.z, w0, acc0[2]);  acc1[2] = fmaf(d0.z, w1, acc1[2]);
                acc0[3] = fmaf(d0.w, w0, acc0[3]);  acc1[3] = fmaf(d0.w, w1, acc1[3]);
                acc0[4] = fmaf(d1.x, w0, acc0[4]);  acc1[4] = fmaf(d1.x, w1, acc1[4]);
                acc0[5] = fmaf(d1.y, w0, acc0[5]);  acc1[5] = fmaf(d1.y, w1, acc1[5]);
                acc0[6] = fmaf(d1.z, w0, acc0[6]);  acc1[6] = fmaf(d1.z, w1, acc1[6]);
            }
        }

        // stage outputs transposed (stride 65 odd -> conflict-free).
        // Writes for invalid samples land in staging slots never flushed.
        #pragma unroll
        for (int mup = 0; mup < 7; mup++) {
            sm[OBASE + (mu * 7 + mup) * OUTSTR + lane]      = acc0[mup];
            sm[OBASE + (mu * 7 + mup) * OUTSTR + lane + 32] = acc1[mup];
        }
    }
    __syncthreads();

    // coalesced flush
    float* go = out + (size_t)base * KOUT;
    for (int i = tid; i < total; i += THREADS_PER_BLK) {
        int s = i / KOUT;
        int c = i - s * KOUT;
        go[i] = sm[OBASE + c * OUTSTR + s];
    }
}

// ---------------------------------------------------------------------------
extern "C" void kernel_launch(void* const* d_in, const int* in_sizes, int n_in,
                              void* d_out, int out_size)
{
    const float* X1   = (const float*)d_in[0];
    const float* X2   = (const float*)d_in[1];
    const float* mult = (const float*)d_in[2];
    const int*   m1   = (const int*)d_in[3];
    const int*   m1p  = (const int*)d_in[4];
    const int*   m2   = (const int*)d_in[5];
    const int*   m2p  = (const int*)d_in[6];
    const int*   mub  = (const int*)d_in[7];

    int n_aligned = in_sizes[2];
    int N = in_sizes[0] / KOUT;

    wigner_setup<<<1, 256>>>(mult, m1, m1p, m2, m2p, mub, n_aligned);

    int grid = (N + SAMPLES_PER_BLK - 1) / SAMPLES_PER_BLK;
    wigner_main<<<grid, THREADS_PER_BLK>>>(X1, X2, (float*)d_out, N);
}

// round 12
// speedup vs baseline: 1.1068x; 1.0217x over previous
#include <cuda_runtime.h>
#include <stdint.h>

#define KOUT 49
#define MAXT 32
#define SAMPLES_PER_BLK 64               // 2 samples per thread: lane and lane+32
#define THREADS_PER_BLK 224              // 7 warps: warp w -> mu = w
#define XSTR 99                          // per-sample X blob: X1[0..48], X2[49..97], pad (odd -> conflict-free)
#define X2B 196                          // byte offset of X2 row 0 in blob
#define OBASE (SAMPLES_PER_BLK * XSTR)   // 6336 words
#define OUTSTR 65                        // odd -> conflict-free transposed staging
#define SMEM_WORDS (OBASE + KOUT * OUTSTR)   // 9521 words = 38084 B

// ---------------------------------------------------------------------------
// Single FUSED kernel. Every block rebuilds the small transformation tables
// in shared memory (overlapped with the X staging loads), then computes.
//
// Table recovery from the aligned product arrays (generation order mu,t,mup,t'):
//   focc[v] (v<7) -> start of (mu=0,t=0,mup=v) run ; focc[mu*7] -> mu segment
//   T[v] = focc[v+1]-focc[v] (v<6); T[6] = focc[7]/T[0] - focc[6]; Ttot = focc[6]+T[6]
// Coefficients from products only (A = mult[0] = c0^2):
//   c_hat(mu,t)   = mult[seg(mu) + t*Ttot]   (= c_t * c0)
//   d_hat(mup,t') = mult[focc[mup] + t'] / A (= c_t' / c0)   =>  c_hat*d_hat exact.
// Stage-1: <=2 terms per (mu, m2-row) (validated R8-R11), fixed uint4 slot
// {off_a, c_a, off_b, c_b}; slots canonicalized by offset for determinism.
// Stage-2: dense D[i][mup], i=(m1p*7+m2p) unique per mup (compress merges) ->
// plain stores, no atomics, deterministic.
// ---------------------------------------------------------------------------
__global__ void __launch_bounds__(THREADS_PER_BLK, 3)
wigner_fused(const float* __restrict__ X1, const float* __restrict__ X2,
             const float* __restrict__ mult,
             const int* __restrict__ m1,  const int* __restrict__ m1p,
             const int* __restrict__ m2,  const int* __restrict__ m2p,
             const int* __restrict__ mub,
             float* __restrict__ out, int N, int n)
{
    __shared__ float sm[SMEM_WORDS];
    __shared__ __align__(16) uint4 s_gslot[49];
    __shared__ __align__(16) float s_D[KOUT * 8];
    __shared__ int s_focc[KOUT];
    __shared__ int s_cnt[KOUT];
    __shared__ int s_sT[8];

    int tid  = threadIdx.x;
    int lane = tid & 31;
    int mu   = tid >> 5;
    int base = blockIdx.x * SAMPLES_PER_BLK;
    int nvalid = N - base; if (nvalid > SAMPLES_PER_BLK) nvalid = SAMPLES_PER_BLK;
    int total = nvalid * KOUT;
    bool full = (nvalid == SAMPLES_PER_BLK);

    const float* g1 = X1 + (size_t)base * KOUT;
    const float* g2 = X2 + (size_t)base * KOUT;

    // ---- init shared table state ----
    if (tid < KOUT) { s_focc[tid] = 0x7fffffff; s_cnt[tid] = 0; s_gslot[tid] = make_uint4(0u,0u,0u,0u); }
    for (int i = tid; i < KOUT * 8; i += THREADS_PER_BLK) s_D[i] = 0.0f;

    // ---- issue X staging LDGs early (MLP=28); latency hides the table build
    float r1v[14], r2v[14];
    if (full) {
        #pragma unroll
        for (int k = 0; k < 14; k++) {
            int i = tid + k * THREADS_PER_BLK;
            r1v[k] = g1[i];
            r2v[k] = g2[i];
        }
    }
    __syncthreads();

    // ---- focc scan over the aligned index (mub is L2-resident: 313 blocks reread)
    for (int j = tid; j < n; j += THREADS_PER_BLK)
        atomicMin(&s_focc[mub[j]], j);

    // ---- STS the X data (loads long since arrived)
    if (full) {
        #pragma unroll
        for (int k = 0; k < 14; k++) {
            int i = tid + k * THREADS_PER_BLK;
            int s = i / KOUT;
            int c = i - s * KOUT;
            sm[s * XSTR + c]      = r1v[k];
            sm[s * XSTR + 49 + c] = r2v[k];
        }
    }
    __syncthreads();

    if (tid == 0) {
        int T0 = s_focc[1] - s_focc[0];
        s_sT[0] = T0;
        for (int v = 1; v < 6; v++) s_sT[v] = s_focc[v + 1] - s_focc[v];
        int t6 = s_focc[7] / T0 - s_focc[6];
        s_sT[6] = t6;
        s_sT[7] = s_focc[6] + t6;                   // Ttot
        for (int v = 0; v < 7; v++) if (s_sT[v] > MAXT) s_sT[v] = MAXT;
    }
    __syncthreads();

    // ---- build tables (one thread per (mu, t) slot; indices are L2-hot)
    {
        float A = mult[0];
        int Ttot = s_sT[7];
        int t = lane;
        if (t < s_sT[mu]) {
            int j = s_focc[mu * 7] + t * Ttot;             // (mu, t, 0, 0)
            int r2 = m2[j];
            int pos = atomicAdd(&s_cnt[mu * 7 + r2], 1);
            if (pos < 2) {
                unsigned* slot = (unsigned*)&s_gslot[mu * 7 + r2];
                slot[pos * 2]     = (unsigned)(m1[j] * 28);
                slot[pos * 2 + 1] = __float_as_uint(mult[j]);
            }
            int j2 = s_focc[mu] + t;                        // (0, 0, mup=mu, t')
            // (m1p,m2p) unique within mup after compress -> plain store
            s_D[(m1p[j2] * 7 + m2p[j2]) * 8 + mu] = mult[j2] / A;
        }
    }
    __syncthreads();
    // canonical slot order (deterministic regardless of atomic race)
    if (tid < 49) {
        uint4 e = s_gslot[tid];
        if (e.w != 0u && e.x > e.z) s_gslot[tid] = make_uint4(e.z, e.w, e.x, e.y);
    }

    // ---- slow-path staging for the tail block
    if (!full) {
        for (int i = tid; i < OBASE; i += THREADS_PER_BLK) sm[i] = 0.0f;
        __syncthreads();
        for (int i = tid; i < total; i += THREADS_PER_BLK) {
            int s = i / KOUT;
            int c = i - s * KOUT;
            sm[s * XSTR + c]      = g1[i];
            sm[s * XSTR + 49 + c] = g2[i];
        }
    }
    __syncthreads();

    // ======================= compute core (R11) =======================
    {
        const char* xc0 = (const char*)(sm + lane * XSTR);
        const char* xc1 = (const char*)(sm + (lane + 32) * XSTR);
        const uint4* gs = s_gslot + mu * 7;
        float acc0[7], acc1[7];
        #pragma unroll
        for (int q = 0; q < 7; q++) { acc0[q] = 0.0f; acc1[q] = 0.0f; }

        // ================= PASS A : rows a = 0..3 =================
        {
            float WA0[28], WA1[28];
            #pragma unroll
            for (int i = 0; i < 28; i++) { WA0[i] = 0.0f; WA1[i] = 0.0f; }
            #pragma unroll 1
            for (int g = 0; g < 7; g++) {
                uint4 e = gs[g];                               // uniform
                float c0 = __uint_as_float(e.y);
                float c1 = __uint_as_float(e.w);
                const float* ra0 = (const float*)(xc0 + e.x);
                const float* rb0 = (const float*)(xc0 + e.z);
                const float* ra1 = (const float*)(xc1 + e.x);
                const float* rb1 = (const float*)(xc1 + e.z);
                float u00 = fmaf(c1, rb0[0], c0 * ra0[0]);
                float u01 = fmaf(c1, rb0[1], c0 * ra0[1]);
                float u02 = fmaf(c1, rb0[2], c0 * ra0[2]);
                float u03 = fmaf(c1, rb0[3], c0 * ra0[3]);
                float u10 = fmaf(c1, rb1[0], c0 * ra1[0]);
                float u11 = fmaf(c1, rb1[1], c0 * ra1[1]);
                float u12 = fmaf(c1, rb1[2], c0 * ra1[2]);
                float u13 = fmaf(c1, rb1[3], c0 * ra1[3]);
                const float* r20 = (const float*)(xc0 + X2B + g * 28);
                const float* r21 = (const float*)(xc1 + X2B + g * 28);
                #pragma unroll
                for (int b = 0; b < 7; b++) {
                    float x0 = r20[b];
                    float x1 = r21[b];
                    WA0[0 * 7 + b] = fmaf(u00, x0, WA0[0 * 7 + b]);
                    WA1[0 * 7 + b] = fmaf(u10, x1, WA1[0 * 7 + b]);
                    WA0[1 * 7 + b] = fmaf(u01, x0, WA0[1 * 7 + b]);
                    WA1[1 * 7 + b] = fmaf(u11, x1, WA1[1 * 7 + b]);
                    WA0[2 * 7 + b] = fmaf(u02, x0, WA0[2 * 7 + b]);
                    WA1[2 * 7 + b] = fmaf(u12, x1, WA1[2 * 7 + b]);
                    WA0[3 * 7 + b] = fmaf(u03, x0, WA0[3 * 7 + b]);
                    WA1[3 * 7 + b] = fmaf(u13, x1, WA1[3 * 7 + b]);
                }
            }
            #pragma unroll
            for (int i = 0; i < 28; i++) {
                float4 d0 = *(const float4*)(s_D + i * 8);     // uniform, shared by both samples
                float4 d1 = *(const float4*)(s_D + i * 8 + 4);
                float w0 = WA0[i], w1 = WA1[i];
                acc0[0] = fmaf(d0.x, w0, acc0[0]);  acc1[0] = fmaf(d0.x, w1, acc1[0]);
                acc0[1] = fmaf(d0.y, w0, acc0[1]);  acc1[1] = fmaf(d0.y, w1, acc1[1]);
                acc0[2] = fmaf(d0.z, w0, acc0[2]);  acc1[2] = fmaf(d0.z, w1, acc1[2]);
                acc0[3] = fmaf(d0.w, w0, acc0[3]);  acc1[3] = fmaf(d0.w, w1, acc1[3]);
                acc0[4] = fmaf(d1.x, w0, acc0[4]);  acc1[4] = fmaf(d1.x, w1, acc1[4]);
                acc0[5] = fmaf(d1.y, w0, acc0[5]);  acc1[5] = fmaf(d1.y, w1, acc1[5]);
                acc0[6] = fmaf(d1.z, w0, acc0[6]);  acc1[6] = fmaf(d1.z, w1, acc1[6]);
            }
        }

        // ================= PASS B : rows a = 4..6 =================
        {
            float WB0[21], WB1[21];
            #pragma unroll
            for (int i = 0; i < 21; i++) { WB0[i] = 0.0f; WB1[i] = 0.0f; }
            #pragma unroll 1
            for (int g = 0; g < 7; g++) {
                uint4 e = gs[g];
                float c0 = __uint_as_float(e.y);
                float c1 = __uint_as_float(e.w);
                const float* ra0 = (const float*)(xc0 + e.x);
                const float* rb0 = (const float*)(xc0 + e.z);
                const float* ra1 = (const float*)(xc1 + e.x);
                const float* rb1 = (const float*)(xc1 + e.z);
                float u04 = fmaf(c1, rb0[4], c0 * ra0[4]);
                float u05 = fmaf(c1, rb0[5], c0 * ra0[5]);
                float u06 = fmaf(c1, rb0[6], c0 * ra0[6]);
                float u14 = fmaf(c1, rb1[4], c0 * ra1[4]);
                float u15 = fmaf(c1, rb1[5], c0 * ra1[5]);
                float u16 = fmaf(c1, rb1[6], c0 * ra1[6]);
                const float* r20 = (const float*)(xc0 + X2B + g * 28);
                const float* r21 = (const float*)(xc1 + X2B + g * 28);
                #pragma unroll
                for (int b = 0; b < 7; b++) {
                    float x0 = r20[b];
                    float x1 = r21[b];
                    WB0[0 * 7 + b] = fmaf(u04, x0, WB0[0 * 7 + b]);
                    WB1[0 * 7 + b] = fmaf(u14, x1, WB1[0 * 7 + b]);
                    WB0[1 * 7 + b] = fmaf(u05, x0, WB0[1 * 7 + b]);
                    WB1[1 * 7 + b] = fmaf(u15, x1, WB1[1 * 7 + b]);
                    WB0[2 * 7 + b] = fmaf(u06, x0, WB0[2 * 7 + b]);
                    WB1[2 * 7 + b] = fmaf(u16, x1, WB1[2 * 7 + b]);
                }
            }
            #pragma unroll
            for (int i = 0; i < 21; i++) {
                float4 d0 = *(const float4*)(s_D + (28 + i) * 8);
                float4 d1 = *(const float4*)(s_D + (28 + i) * 8 + 4);
                float w0 = WB0[i], w1 = WB1[i];
                acc0[0] = fmaf(d0.x, w0, acc0[0]);  acc1[0] = fmaf(d0.x, w1, acc1[0]);
                acc0[1] = fmaf(d0.y, w0, acc0[1]);  acc1[1] = fmaf(d0.y, w1, acc1[1]);
                acc0[2] = fmaf(d0.z, w0, acc0[2]);  acc1[2] = fmaf(d0.z, w1, acc1[2]);
                acc0[3] = fmaf(d0.w, w0, acc0[3]);  acc1[3] = fmaf(d0.w, w1, acc1[3]);
                acc0[4] = fmaf(d1.x, w0, acc0[4]);  acc1[4] = fmaf(d1.x, w1, acc1[4]);
                acc0[5] = fmaf(d1.y, w0, acc0[5]);  acc1[5] = fmaf(d1.y, w1, acc1[5]);
                acc0[6] = fmaf(d1.z, w0, acc0[6]);  acc1[6] = fmaf(d1.z, w1, acc1[6]);
            }
        }

        // stage outputs transposed (stride 65 odd -> conflict-free).
        #pragma unroll
        for (int mup = 0; mup < 7; mup++) {
            sm[OBASE + (mu * 7 + mup) * OUTSTR + lane]      = acc0[mup];
            sm[OBASE + (mu * 7 + mup) * OUTSTR + lane + 32] = acc1[mup];
        }
    }
    __syncthreads();

    // coalesced flush
    float* go = out + (size_t)base * KOUT;
    for (int i = tid; i < total; i += THREADS_PER_BLK) {
        int s = i / KOUT;
        int c = i - s * KOUT;
        go[i] = sm[OBASE + c * OUTSTR + s];
    }
}

// ---------------------------------------------------------------------------
extern "C" void kernel_launch(void* const* d_in, const int* in_sizes, int n_in,
                              void* d_out, int out_size)
{
    const float* X1   = (const float*)d_in[0];
    const float* X2   = (const float*)d_in[1];
    const float* mult = (const float*)d_in[2];
    const int*   m1   = (const int*)d_in[3];
    const int*   m1p  = (const int*)d_in[4];
    const int*   m2   = (const int*)d_in[5];
    const int*   m2p  = (const int*)d_in[6];
    const int*   mub  = (const int*)d_in[7];

    int n_aligned = in_sizes[2];
    int N = in_sizes[0] / KOUT;

    int grid = (N + SAMPLES_PER_BLK - 1) / SAMPLES_PER_BLK;
    wigner_fused<<<grid, THREADS_PER_BLK>>>(X1, X2, mult, m1, m1p, m2, m2p, mub,
                                            (float*)d_out, N, n_aligned);
}

// round 13
// speedup vs baseline: 1.2557x; 1.1345x over previous
#include <cuda_runtime.h>
#include <stdint.h>
#include <math.h>

#define KOUT 49
#define MAXT 32
#define SAMPLES_PER_BLK 64               // 2 samples per thread: lane and lane+32
#define THREADS_PER_BLK 224              // 7 warps: warp w -> mu = w
#define XSTR 99                          // per-sample X blob: X1[0..48], X2[49..97], pad (odd -> conflict-free)
#define X2B 196                          // byte offset of X2 row 0 in blob
#define OBASE (SAMPLES_PER_BLK * XSTR)   // 6336 words
#define OUTSTR 65                        // odd -> conflict-free transposed staging
#define SMEM_WORDS (OBASE + KOUT * OUTSTR)   // 9521 words = 38084 B

// ---------------------------------------------------------------------------
// Single FUSED kernel; every block rebuilds the tiny tables in shared memory,
// overlapped with the X staging loads. KEY (R13): no full scan of the aligned
// array needed —
//   n = Ttot^2 exactly (aligned set is the product of two term lists)
//       => Ttot = round(sqrt(n))
//   focc[v], v=0..6 all lie in the first (mu=0,t=0) run (j < Ttot <= 224)
//       => ONE round of mub[tid] + predicated atomicMin recovers them
//   seg(mu) = Ttot * focc[mu];  T[v] = focc[v+1]-focc[v], T[6] = Ttot-focc[6]
// Coefficients from products only (A = mult[0] = c0^2):
//   c_hat(mu,t)   = mult[Ttot*(focc[mu]+t)]  (= c_t * c0)
//   d_hat(mup,t') = mult[focc[mup]+t'] / A   (= c_t' / c0)  => c_hat*d_hat exact.
// Stage-1: <=2 terms per (mu, m2-row) (validated R8-R12), fixed uint4 slot,
// canonicalized by offset. Stage-2: dense D[i][mup], (m1p,m2p) unique per mup
// after compress -> plain stores, deterministic.
// ---------------------------------------------------------------------------
__global__ void __launch_bounds__(THREADS_PER_BLK, 3)
wigner_fused(const float* __restrict__ X1, const float* __restrict__ X2,
             const float* __restrict__ mult,
             const int* __restrict__ m1,  const int* __restrict__ m1p,
             const int* __restrict__ m2,  const int* __restrict__ m2p,
             const int* __restrict__ mub,
             float* __restrict__ out, int N, int n)
{
    __shared__ float sm[SMEM_WORDS];
    __shared__ __align__(16) uint4 s_gslot[49];
    __shared__ __align__(16) float s_D[KOUT * 8];
    __shared__ int s_focc[8];
    __shared__ int s_cnt[KOUT];
    __shared__ int s_sT[8];

    int tid  = threadIdx.x;
    int lane = tid & 31;
    int mu   = tid >> 5;
    int base = blockIdx.x * SAMPLES_PER_BLK;
    int nvalid = N - base; if (nvalid > SAMPLES_PER_BLK) nvalid = SAMPLES_PER_BLK;
    int total = nvalid * KOUT;
    bool full = (nvalid == SAMPLES_PER_BLK);

    const float* g1 = X1 + (size_t)base * KOUT;
    const float* g2 = X2 + (size_t)base * KOUT;

    // ---- init shared table state ----
    if (tid < 8)    s_focc[tid] = 0x7fffffff;
    if (tid < KOUT) { s_cnt[tid] = 0; s_gslot[tid] = make_uint4(0u,0u,0u,0u); }
    for (int i = tid; i < KOUT * 8; i += THREADS_PER_BLK) s_D[i] = 0.0f;

    // ---- issue X staging LDGs early (MLP=28); latency hides the table build
    float r1v[14], r2v[14];
    if (full) {
        #pragma unroll
        for (int k = 0; k < 14; k++) {
            int i = tid + k * THREADS_PER_BLK;
            r1v[k] = g1[i];
            r2v[k] = g2[i];
        }
    }
    __syncthreads();

    // ---- focc recovery: ONE round over the first <=224 aligned entries
    if (tid < n) {
        int v = mub[tid];
        if (v < 7) atomicMin(&s_focc[v], tid);
    }

    // ---- STS the X data (loads arrive under the atomic round)
    if (full) {
        #pragma unroll
        for (int k = 0; k < 14; k++) {
            int i = tid + k * THREADS_PER_BLK;
            int s = i / KOUT;
            int c = i - s * KOUT;
            sm[s * XSTR + c]      = r1v[k];
            sm[s * XSTR + 49 + c] = r2v[k];
        }
    }
    __syncthreads();

    if (tid == 0) {
        int Ttot = (int)(sqrtf((float)n) + 0.5f);   // n = Ttot^2 exactly
        s_focc[0] = 0;
        s_sT[7] = Ttot;
        for (int v = 0; v < 6; v++) s_sT[v] = s_focc[v + 1] - s_focc[v];
        s_sT[6] = Ttot - s_focc[6];
        for (int v = 0; v < 7; v++) if (s_sT[v] > MAXT) s_sT[v] = MAXT;
    }
    __syncthreads();

    // ---- build tables (one thread per (mu, t) slot; index arrays L2-hot)
    {
        float A = mult[0];
        int Ttot = s_sT[7];
        int t = lane;
        if (t < s_sT[mu]) {
            int j = Ttot * (s_focc[mu] + t);               // (mu, t, 0, 0)
            int r2 = m2[j];
            int pos = atomicAdd(&s_cnt[mu * 7 + r2], 1);
            if (pos < 2) {
                unsigned* slot = (unsigned*)&s_gslot[mu * 7 + r2];
                slot[pos * 2]     = (unsigned)(m1[j] * 28);
                slot[pos * 2 + 1] = __float_as_uint(mult[j]);
            }
            int j2 = s_focc[mu] + t;                        // (0, 0, mup=mu, t')
            s_D[(m1p[j2] * 7 + m2p[j2]) * 8 + mu] = mult[j2] / A;  // unique -> plain store
        }
    }
    __syncthreads();
    // canonical slot order (deterministic regardless of atomic race)
    if (tid < 49) {
        uint4 e = s_gslot[tid];
        if (e.w != 0u && e.x > e.z) s_gslot[tid] = make_uint4(e.z, e.w, e.x, e.y);
    }

    // ---- slow-path staging for the tail block
    if (!full) {
        for (int i = tid; i < OBASE; i += THREADS_PER_BLK) sm[i] = 0.0f;
        __syncthreads();
        for (int i = tid; i < total; i += THREADS_PER_BLK) {
            int s = i / KOUT;
            int c = i - s * KOUT;
            sm[s * XSTR + c]      = g1[i];
            sm[s * XSTR + 49 + c] = g2[i];
        }
    }
    __syncthreads();

    // ======================= compute core (R11) =======================
    {
        const char* xc0 = (const char*)(sm + lane * XSTR);
        const char* xc1 = (const char*)(sm + (lane + 32) * XSTR);
        const uint4* gs = s_gslot + mu * 7;
        float acc0[7], acc1[7];
        #pragma unroll
        for (int q = 0; q < 7; q++) { acc0[q] = 0.0f; acc1[q] = 0.0f; }

        // ================= PASS A : rows a = 0..3 =================
        {
            float WA0[28], WA1[28];
            #pragma unroll
            for (int i = 0; i < 28; i++) { WA0[i] = 0.0f; WA1[i] = 0.0f; }
            #pragma unroll 1
            for (int g = 0; g < 7; g++) {
                uint4 e = gs[g];                               // uniform
                float c0 = __uint_as_float(e.y);
                float c1 = __uint_as_float(e.w);
                const float* ra0 = (const float*)(xc0 + e.x);
                const float* rb0 = (const float*)(xc0 + e.z);
                const float* ra1 = (const float*)(xc1 + e.x);
                const float* rb1 = (const float*)(xc1 + e.z);
                float u00 = fmaf(c1, rb0[0], c0 * ra0[0]);
                float u01 = fmaf(c1, rb0[1], c0 * ra0[1]);
                float u02 = fmaf(c1, rb0[2], c0 * ra0[2]);
                float u03 = fmaf(c1, rb0[3], c0 * ra0[3]);
                float u10 = fmaf(c1, rb1[0], c0 * ra1[0]);
                float u11 = fmaf(c1, rb1[1], c0 * ra1[1]);
                float u12 = fmaf(c1, rb1[2], c0 * ra1[2]);
                float u13 = fmaf(c1, rb1[3], c0 * ra1[3]);
                const float* r20 = (const float*)(xc0 + X2B + g * 28);
                const float* r21 = (const float*)(xc1 + X2B + g * 28);
                #pragma unroll
                for (int b = 0; b < 7; b++) {
                    float x0 = r20[b];
                    float x1 = r21[b];
                    WA0[0 * 7 + b] = fmaf(u00, x0, WA0[0 * 7 + b]);
                    WA1[0 * 7 + b] = fmaf(u10, x1, WA1[0 * 7 + b]);
                    WA0[1 * 7 + b] = fmaf(u01, x0, WA0[1 * 7 + b]);
                    WA1[1 * 7 + b] = fmaf(u11, x1, WA1[1 * 7 + b]);
                    WA0[2 * 7 + b] = fmaf(u02, x0, WA0[2 * 7 + b]);
                    WA1[2 * 7 + b] = fmaf(u12, x1, WA1[2 * 7 + b]);
                    WA0[3 * 7 + b] = fmaf(u03, x0, WA0[3 * 7 + b]);
                    WA1[3 * 7 + b] = fmaf(u13, x1, WA1[3 * 7 + b]);
                }
            }
            #pragma unroll
            for (int i = 0; i < 28; i++) {
                float4 d0 = *(const float4*)(s_D + i * 8);     // uniform, shared by both samples
                float4 d1 = *(const float4*)(s_D + i * 8 + 4);
                float w0 = WA0[i], w1 = WA1[i];
                acc0[0] = fmaf(d0.x, w0, acc0[0]);  acc1[0] = fmaf(d0.x, w1, acc1[0]);
                acc0[1] = fmaf(d0.y, w0, acc0[1]);  acc1[1] = fmaf(d0.y, w1, acc1[1]);
                acc0[2] = fmaf(d0.z, w0, acc0[2]);  acc1[2] = fmaf(d0.z, w1, acc1[2]);
                acc0[3] = fmaf(d0.w, w0, acc0[3]);  acc1[3] = fmaf(d0.w, w1, acc1[3]);
                acc0[4] = fmaf(d1.x, w0, acc0[4]);  acc1[4] = fmaf(d1.x, w1, acc1[4]);
                acc0[5] = fmaf(d1.y, w0, acc0[5]);  acc1[5] = fmaf(d1.y, w1, acc1[5]);
                acc0[6] = fmaf(d1.z, w0, acc0[6]);  acc1[6] = fmaf(d1.z, w1, acc1[6]);
            }
        }

        // ================= PASS B : rows a = 4..6 =================
        {
            float WB0[21], WB1[21];
            #pragma unroll
            for (int i = 0; i < 21; i++) { WB0[i] = 0.0f; WB1[i] = 0.0f; }
            #pragma unroll 1
            for (int g = 0; g < 7; g++) {
                uint4 e = gs[g];
                float c0 = __uint_as_float(e.y);
                float c1 = __uint_as_float(e.w);
                const float* ra0 = (const float*)(xc0 + e.x);
                const float* rb0 = (const float*)(xc0 + e.z);
                const float* ra1 = (const float*)(xc1 + e.x);
                const float* rb1 = (const float*)(xc1 + e.z);
                float u04 = fmaf(c1, rb0[4], c0 * ra0[4]);
                float u05 = fmaf(c1, rb0[5], c0 * ra0[5]);
                float u06 = fmaf(c1, rb0[6], c0 * ra0[6]);
                float u14 = fmaf(c1, rb1[4], c0 * ra1[4]);
                float u15 = fmaf(c1, rb1[5], c0 * ra1[5]);
                float u16 = fmaf(c1, rb1[6], c0 * ra1[6]);
                const float* r20 = (const float*)(xc0 + X2B + g * 28);
                const float* r21 = (const float*)(xc1 + X2B + g * 28);
                #pragma unroll
                for (int b = 0; b < 7; b++) {
                    float x0 = r20[b];
                    float x1 = r21[b];
                    WB0[0 * 7 + b] = fmaf(u04, x0, WB0[0 * 7 + b]);
                    WB1[0 * 7 + b] = fmaf(u14, x1, WB1[0 * 7 + b]);
                    WB0[1 * 7 + b] = fmaf(u05, x0, WB0[1 * 7 + b]);
                    WB1[1 * 7 + b] = fmaf(u15, x1, WB1[1 * 7 + b]);
                    WB0[2 * 7 + b] = fmaf(u06, x0, WB0[2 * 7 + b]);
                    WB1[2 * 7 + b] = fmaf(u16, x1, WB1[2 * 7 + b]);
                }
            }
            #pragma unroll
            for (int i = 0; i < 21; i++) {
                float4 d0 = *(const float4*)(s_D + (28 + i) * 8);
                float4 d1 = *(const float4*)(s_D + (28 + i) * 8 + 4);
                float w0 = WB0[i], w1 = WB1[i];
                acc0[0] = fmaf(d0.x, w0, acc0[0]);  acc1[0] = fmaf(d0.x, w1, acc1[0]);
                acc0[1] = fmaf(d0.y, w0, acc0[1]);  acc1[1] = fmaf(d0.y, w1, acc1[1]);
                acc0[2] = fmaf(d0.z, w0, acc0[2]);  acc1[2] = fmaf(d0.z, w1, acc1[2]);
                acc0[3] = fmaf(d0.w, w0, acc0[3]);  acc1[3] = fmaf(d0.w, w1, acc1[3]);
                acc0[4] = fmaf(d1.x, w0, acc0[4]);  acc1[4] = fmaf(d1.x, w1, acc1[4]);
                acc0[5] = fmaf(d1.y, w0, acc0[5]);  acc1[5] = fmaf(d1.y, w1, acc1[5]);
                acc0[6] = fmaf(d1.z, w0, acc0[6]);  acc1[6] = fmaf(d1.z, w1, acc1[6]);
            }
        }

        // stage outputs transposed (stride 65 odd -> conflict-free).
        #pragma unroll
        for (int mup = 0; mup < 7; mup++) {
            sm[OBASE + (mu * 7 + mup) * OUTSTR + lane]      = acc0[mup];
            sm[OBASE + (mu * 7 + mup) * OUTSTR + lane + 32] = acc1[mup];
        }
    }
    __syncthreads();

    // coalesced flush
    float* go = out + (size_t)base * KOUT;
    for (int i = tid; i < total; i += THREADS_PER_BLK) {
        int s = i / KOUT;
        int c = i - s * KOUT;
        go[i] = sm[OBASE + c * OUTSTR + s];
    }
}

// ---------------------------------------------------------------------------
extern "C" void kernel_launch(void* const* d_in, const int* in_sizes, int n_in,
                              void* d_out, int out_size)
{
    const float* X1   = (const float*)d_in[0];
    const float* X2   = (const float*)d_in[1];
    const float* mult = (const float*)d_in[2];
    const int*   m1   = (const int*)d_in[3];
    const int*   m1p  = (const int*)d_in[4];
    const int*   m2   = (const int*)d_in[5];
    const int*   m2p  = (const int*)d_in[6];
    const int*   mub  = (const int*)d_in[7];

    int n_aligned = in_sizes[2];
    int N = in_sizes[0] / KOUT;

    int grid = (N + SAMPLES_PER_BLK - 1) / SAMPLES_PER_BLK;
    wigner_fused<<<grid, THREADS_PER_BLK>>>(X1, X2, mult, m1, m1p, m2, m2p, mub,
                                            (float*)d_out, N, n_aligned);
}

// round 14
// speedup vs baseline: 1.2581x; 1.0019x over previous
#include <cuda_runtime.h>
#include <stdint.h>
#include <math.h>

#define KOUT 49
#define MAXT 32
#define SAMPLES_PER_BLK 64               // 2 samples per thread: lane and lane+32
#define THREADS_PER_BLK 224              // 7 warps: warp w -> mu = w
#define XSTR 99                          // per-sample X blob: X1[0..48], X2[49..97], pad (odd -> conflict-free)
#define X2B 196                          // byte offset of X2 row 0 in blob
#define OBASE (SAMPLES_PER_BLK * XSTR)   // 6336 words
#define OUTSTR 65                        // odd -> conflict-free transposed staging
#define SMEM_WORDS (OBASE + KOUT * OUTSTR)   // 9521 words = 38084 B

// ---- packed f32x2 helpers (sm_103a FFMA2: PTX-only, per SASS_QUICKREF) ----
__device__ __forceinline__ unsigned long long pk2(float lo, float hi) {
    unsigned long long r;
    asm("mov.b64 %0, {%1, %2};" : "=l"(r)
        : "r"(__float_as_uint(lo)), "r"(__float_as_uint(hi)));
    return r;
}
__device__ __forceinline__ unsigned long long fma2(unsigned long long a,
                                                   unsigned long long b,
                                                   unsigned long long c) {
    unsigned long long r;
    asm("fma.rn.f32x2 %0, %1, %2, %3;" : "=l"(r) : "l"(a), "l"(b), "l"(c));
    return r;
}
__device__ __forceinline__ unsigned long long mul2(unsigned long long a,
                                                   unsigned long long b) {
    unsigned long long r;
    asm("mul.rn.f32x2 %0, %1, %2;" : "=l"(r) : "l"(a), "l"(b));
    return r;
}
__device__ __forceinline__ void upk2(unsigned long long v, float& lo, float& hi) {
    unsigned l, h;
    asm("mov.b64 {%0, %1}, %2;" : "=r"(l), "=r"(h) : "l"(v));
    lo = __uint_as_float(l); hi = __uint_as_float(h);
}

// ---------------------------------------------------------------------------
// Single FUSED kernel (R13 skeleton). Table recovery (O(1), no full scan):
//   n = Ttot^2 exactly  => Ttot = round(sqrt(n))
//   focc[v] v=0..6 lie in the first Ttot<=224 entries => one predicated
//   atomicMin round over mub[tid] recovers them.
//   seg(mu) = Ttot*focc[mu]; T[v] = focc[v+1]-focc[v], T[6] = Ttot-focc[6]
// Coefficients from products only (A = mult[0] = c0^2):
//   c_hat(mu,t) = mult[Ttot*(focc[mu]+t)], d_hat = mult[focc[mup]+t']/A.
// Stage-1: <=2 terms per (mu, m2-row), fixed uint4 slot, canonical order.
// Stage-2: dense D stored PRE-DUPLICATED as (d,d) f32x2 pairs.
// R14: all per-sample-duplicated FMAs fused into f32x2 pairs (sample0,sample1).
// ---------------------------------------------------------------------------
__global__ void __launch_bounds__(THREADS_PER_BLK, 3)
wigner_fused(const float* __restrict__ X1, const float* __restrict__ X2,
             const float* __restrict__ mult,
             const int* __restrict__ m1,  const int* __restrict__ m1p,
             const int* __restrict__ m2,  const int* __restrict__ m2p,
             const int* __restrict__ mub,
             float* __restrict__ out, int N, int n)
{
    __shared__ float sm[SMEM_WORDS];
    __shared__ __align__(16) uint4 s_gslot[49];
    __shared__ __align__(16) unsigned long long s_D2[KOUT * 8];  // (d,d) pairs, row padded to 8
    __shared__ int s_focc[8];
    __shared__ int s_cnt[KOUT];
    __shared__ int s_sT[8];

    int tid  = threadIdx.x;
    int lane = tid & 31;
    int mu   = tid >> 5;
    int base = blockIdx.x * SAMPLES_PER_BLK;
    int nvalid = N - base; if (nvalid > SAMPLES_PER_BLK) nvalid = SAMPLES_PER_BLK;
    int total = nvalid * KOUT;
    bool full = (nvalid == SAMPLES_PER_BLK);

    const float* g1 = X1 + (size_t)base * KOUT;
    const float* g2 = X2 + (size_t)base * KOUT;

    // ---- init shared table state ----
    if (tid < 8)    s_focc[tid] = 0x7fffffff;
    if (tid < KOUT) { s_cnt[tid] = 0; s_gslot[tid] = make_uint4(0u,0u,0u,0u); }
    for (int i = tid; i < KOUT * 8; i += THREADS_PER_BLK) s_D2[i] = 0ULL;

    // ---- issue X staging LDGs early (MLP=28); latency hides the table build
    float r1v[14], r2v[14];
    if (full) {
        #pragma unroll
        for (int k = 0; k < 14; k++) {
            int i = tid + k * THREADS_PER_BLK;
            r1v[k] = g1[i];
            r2v[k] = g2[i];
        }
    }
    __syncthreads();

    // ---- focc recovery: ONE round over the first <=224 aligned entries
    if (tid < n) {
        int v = mub[tid];
        if (v < 7) atomicMin(&s_focc[v], tid);
    }

    // ---- STS the X data (loads arrive under the atomic round)
    if (full) {
        #pragma unroll
        for (int k = 0; k < 14; k++) {
            int i = tid + k * THREADS_PER_BLK;
            int s = i / KOUT;
            int c = i - s * KOUT;
            sm[s * XSTR + c]      = r1v[k];
            sm[s * XSTR + 49 + c] = r2v[k];
        }
    }
    __syncthreads();

    if (tid == 0) {
        int Ttot = (int)(sqrtf((float)n) + 0.5f);   // n = Ttot^2 exactly
        s_focc[0] = 0;
        s_sT[7] = Ttot;
        for (int v = 0; v < 6; v++) s_sT[v] = s_focc[v + 1] - s_focc[v];
        s_sT[6] = Ttot - s_focc[6];
        for (int v = 0; v < 7; v++) if (s_sT[v] > MAXT) s_sT[v] = MAXT;
    }
    __syncthreads();

    // ---- build tables (one thread per (mu, t) slot; index arrays L2-hot)
    {
        float A = mult[0];
        int Ttot = s_sT[7];
        int t = lane;
        if (t < s_sT[mu]) {
            int j = Ttot * (s_focc[mu] + t);               // (mu, t, 0, 0)
            int r2 = m2[j];
            int pos = atomicAdd(&s_cnt[mu * 7 + r2], 1);
            if (pos < 2) {
                unsigned* slot = (unsigned*)&s_gslot[mu * 7 + r2];
                slot[pos * 2]     = (unsigned)(m1[j] * 28);
                slot[pos * 2 + 1] = __float_as_uint(mult[j]);
            }
            int j2 = s_focc[mu] + t;                        // (0, 0, mup=mu, t')
            float d = mult[j2] / A;                         // unique -> plain store
            s_D2[(m1p[j2] * 7 + m2p[j2]) * 8 + mu] = pk2(d, d);
        }
    }
    __syncthreads();
    // canonical slot order (deterministic regardless of atomic race)
    if (tid < 49) {
        uint4 e = s_gslot[tid];
        if (e.w != 0u && e.x > e.z) s_gslot[tid] = make_uint4(e.z, e.w, e.x, e.y);
    }

    // ---- slow-path staging for the tail block
    if (!full) {
        for (int i = tid; i < OBASE; i += THREADS_PER_BLK) sm[i] = 0.0f;
        __syncthreads();
        for (int i = tid; i < total; i += THREADS_PER_BLK) {
            int s = i / KOUT;
            int c = i - s * KOUT;
            sm[s * XSTR + c]      = g1[i];
            sm[s * XSTR + 49 + c] = g2[i];
        }
    }
    __syncthreads();

    // ======================= compute core (f32x2-paired) =======================
    {
        const char* xc0 = (const char*)(sm + lane * XSTR);
        const char* xc1 = (const char*)(sm + (lane + 32) * XSTR);
        const uint4* gs = s_gslot + mu * 7;
        unsigned long long accp[7];
        #pragma unroll
        for (int q = 0; q < 7; q++) accp[q] = 0ULL;

        // ================= PASS A : rows a = 0..3 =================
        {
            unsigned long long WA[28];
            #pragma unroll
            for (int i = 0; i < 28; i++) WA[i] = 0ULL;
            #pragma unroll 1
            for (int g = 0; g < 7; g++) {
                uint4 e = gs[g];                               // uniform
                float c0 = __uint_as_float(e.y);
                float c1 = __uint_as_float(e.w);
                unsigned long long c0d = pk2(c0, c0);
                unsigned long long c1d = pk2(c1, c1);
                const float* ra0 = (const float*)(xc0 + e.x);
                const float* rb0 = (const float*)(xc0 + e.z);
                const float* ra1 = (const float*)(xc1 + e.x);
                const float* rb1 = (const float*)(xc1 + e.z);
                unsigned long long u[4];
                #pragma unroll
                for (int a = 0; a < 4; a++)
                    u[a] = fma2(c1d, pk2(rb0[a], rb1[a]),
                                mul2(c0d, pk2(ra0[a], ra1[a])));
                const float* r20 = (const float*)(xc0 + X2B + g * 28);
                const float* r21 = (const float*)(xc1 + X2B + g * 28);
                #pragma unroll
                for (int b = 0; b < 7; b++) {
                    unsigned long long xp = pk2(r20[b], r21[b]);
                    WA[0 * 7 + b] = fma2(u[0], xp, WA[0 * 7 + b]);
                    WA[1 * 7 + b] = fma2(u[1], xp, WA[1 * 7 + b]);
                    WA[2 * 7 + b] = fma2(u[2], xp, WA[2 * 7 + b]);
                    WA[3 * 7 + b] = fma2(u[3], xp, WA[3 * 7 + b]);
                }
            }
            #pragma unroll
            for (int i = 0; i < 28; i++) {
                const ulonglong2* dp = (const ulonglong2*)(s_D2 + i * 8);
                ulonglong2 q0 = dp[0];                 // (D[i][0],D[i][1]) dup'd
                ulonglong2 q1 = dp[1];
                ulonglong2 q2 = dp[2];
                unsigned long long q3 = s_D2[i * 8 + 6];
                unsigned long long w = WA[i];
                accp[0] = fma2(q0.x, w, accp[0]);
                accp[1] = fma2(q0.y, w, accp[1]);
                accp[2] = fma2(q1.x, w, accp[2]);
                accp[3] = fma2(q1.y, w, accp[3]);
                accp[4] = fma2(q2.x, w, accp[4]);
                accp[5] = fma2(q2.y, w, accp[5]);
                accp[6] = fma2(q3,   w, accp[6]);
            }
        }

        // ================= PASS B : rows a = 4..6 =================
        {
            unsigned long long WB[21];
            #pragma unroll
            for (int i = 0; i < 21; i++) WB[i] = 0ULL;
            #pragma unroll 1
            for (int g = 0; g < 7; g++) {
                uint4 e = gs[g];
                float c0 = __uint_as_float(e.y);
                float c1 = __uint_as_float(e.w);
                unsigned long long c0d = pk2(c0, c0);
                unsigned long long c1d = pk2(c1, c1);
                const float* ra0 = (const float*)(xc0 + e.x);
                const float* rb0 = (const float*)(xc0 + e.z);
                const float* ra1 = (const float*)(xc1 + e.x);
                const float* rb1 = (const float*)(xc1 + e.z);
                unsigned long long u[3];
                #pragma unroll
                for (int a = 0; a < 3; a++)
                    u[a] = fma2(c1d, pk2(rb0[4 + a], rb1[4 + a]),
                                mul2(c0d, pk2(ra0[4 + a], ra1[4 + a])));
                const float* r20 = (const float*)(xc0 + X2B + g * 28);
                const float* r21 = (const float*)(xc1 + X2B + g * 28);
                #pragma unroll
                for (int b = 0; b < 7; b++) {
                    unsigned long long xp = pk2(r20[b], r21[b]);
                    WB[0 * 7 + b] = fma2(u[0], xp, WB[0 * 7 + b]);
                    WB[1 * 7 + b] = fma2(u[1], xp, WB[1 * 7 + b]);
                    WB[2 * 7 + b] = fma2(u[2], xp, WB[2 * 7 + b]);
                }
            }
            #pragma unroll
            for (int i = 0; i < 21; i++) {
                const ulonglong2* dp = (const ulonglong2*)(s_D2 + (28 + i) * 8);
                ulonglong2 q0 = dp[0];
                ulonglong2 q1 = dp[1];
                ulonglong2 q2 = dp[2];
                unsigned long long q3 = s_D2[(28 + i) * 8 + 6];
                unsigned long long w = WB[i];
                accp[0] = fma2(q0.x, w, accp[0]);
                accp[1] = fma2(q0.y, w, accp[1]);
                accp[2] = fma2(q1.x, w, accp[2]);
                accp[3] = fma2(q1.y, w, accp[3]);
                accp[4] = fma2(q2.x, w, accp[4]);
                accp[5] = fma2(q2.y, w, accp[5]);
                accp[6] = fma2(q3,   w, accp[6]);
            }
        }

        // stage outputs transposed (stride 65 odd -> conflict-free)
        #pragma unroll
        for (int mup = 0; mup < 7; mup++) {
            float a0, a1;
            upk2(accp[mup], a0, a1);
            sm[OBASE + (mu * 7 + mup) * OUTSTR + lane]      = a0;
            sm[OBASE + (mu * 7 + mup) * OUTSTR + lane + 32] = a1;
        }
    }
    __syncthreads();

    // coalesced flush
    float* go = out + (size_t)base * KOUT;
    for (int i = tid; i < total; i += THREADS_PER_BLK) {
        int s = i / KOUT;
        int c = i - s * KOUT;
        go[i] = sm[OBASE + c * OUTSTR + s];
    }
}

// ---------------------------------------------------------------------------
extern "C" void kernel_launch(void* const* d_in, const int* in_sizes, int n_in,
                              void* d_out, int out_size)
{
    const float* X1   = (const float*)d_in[0];
    const float* X2   = (const float*)d_in[1];
    const float* mult = (const float*)d_in[2];
    const int*   m1   = (const int*)d_in[3];
    const int*   m1p  = (const int*)d_in[4];
    const int*   m2   = (const int*)d_in[5];
    const int*   m2p  = (const int*)d_in[6];
    const int*   mub  = (const int*)d_in[7];

    int n_aligned = in_sizes[2];
    int N = in_sizes[0] / KOUT;

    int grid = (N + SAMPLES_PER_BLK - 1) / SAMPLES_PER_BLK;
    wigner_fused<<<grid, THREADS_PER_BLK>>>(X1, X2, mult, m1, m1p, m2, m2p, mub,
                                            (float*)d_out, N, n_aligned);
}